// round 2
// baseline (speedup 1.0000x reference)
#include <cuda_runtime.h>
#include <cuda_bf16.h>
#include <stdint.h>

#define TPB 256
#define TOK 256          // tokens per CTA
#define APP 264          // A' pitch in bf16 elems (132 words; 132%32==4 -> ldmatrix conflict-free)
#define WP  72           // W pitch in bf16 elems (36 words; 36%32==4 -> conflict-free)

struct Smem {
  __nv_bfloat16 Ap[TOK * APP];   // gate-scaled activations [256 tokens][256 (=4 experts x 64)]
  __nv_bfloat16 Wa[256 * WP];    // W'_a [K=256][N=64]
  __nv_bfloat16 Wb[256 * WP];    // W'_b
  float gates[TOK * 4];
  float ca[256];                 // c_a[e*64+f] = (b_a_e @ W_a_e)[f]
  float cb[256];
  float wga[256];                // w_gate_a [64][4]
  float wgb[256];
};

static __device__ __forceinline__ void ldm_x4(uint32_t addr, uint32_t& r0, uint32_t& r1,
                                              uint32_t& r2, uint32_t& r3) {
  asm volatile("ldmatrix.sync.aligned.m8n8.x4.shared.b16 {%0,%1,%2,%3}, [%4];"
               : "=r"(r0), "=r"(r1), "=r"(r2), "=r"(r3) : "r"(addr));
}
static __device__ __forceinline__ void ldm_x4_t(uint32_t addr, uint32_t& r0, uint32_t& r1,
                                                uint32_t& r2, uint32_t& r3) {
  asm volatile("ldmatrix.sync.aligned.m8n8.x4.trans.shared.b16 {%0,%1,%2,%3}, [%4];"
               : "=r"(r0), "=r"(r1), "=r"(r2), "=r"(r3) : "r"(addr));
}
static __device__ __forceinline__ void mma_16816(float* c,
                                                 uint32_t a0, uint32_t a1, uint32_t a2, uint32_t a3,
                                                 uint32_t b0, uint32_t b1) {
  asm volatile("mma.sync.aligned.m16n8k16.row.col.f32.bf16.bf16.f32 "
               "{%0,%1,%2,%3},{%4,%5,%6,%7},{%8,%9},{%0,%1,%2,%3};"
               : "+f"(c[0]), "+f"(c[1]), "+f"(c[2]), "+f"(c[3])
               : "r"(a0), "r"(a1), "r"(a2), "r"(a3), "r"(b0), "r"(b1));
}

// [256 x 256] @ [256 x 64] -> acc.  Warp computes rows [warp*32, warp*32+32).
static __device__ __forceinline__ void gemm256(const __nv_bfloat16* Ap, const __nv_bfloat16* W,
                                               float acc[2][8][4], int warp, int lane) {
  const int m0 = warp * 32;
  uint32_t apBase = (uint32_t)__cvta_generic_to_shared(Ap);
  uint32_t wBase  = (uint32_t)__cvta_generic_to_shared(W);
  const int arow  = lane & 15;
  const int acolh = (lane >> 4) * 8;
  const int bk    = (lane & 7) + ((lane >> 3) & 1) * 8;
  const int bn    = (lane >> 4) * 8;
  #pragma unroll 4
  for (int ks = 0; ks < 16; ks++) {
    uint32_t a[2][4];
    #pragma unroll
    for (int mt = 0; mt < 2; mt++) {
      uint32_t addr = apBase + 2u * (uint32_t)((m0 + mt * 16 + arow) * APP + ks * 16 + acolh);
      ldm_x4(addr, a[mt][0], a[mt][1], a[mt][2], a[mt][3]);
    }
    #pragma unroll
    for (int ntp = 0; ntp < 4; ntp++) {
      uint32_t b0, b1, b2, b3;
      uint32_t baddr = wBase + 2u * (uint32_t)((ks * 16 + bk) * WP + ntp * 16 + bn);
      ldm_x4_t(baddr, b0, b1, b2, b3);
      mma_16816(acc[0][2 * ntp],     a[0][0], a[0][1], a[0][2], a[0][3], b0, b1);
      mma_16816(acc[0][2 * ntp + 1], a[0][0], a[0][1], a[0][2], a[0][3], b2, b3);
      mma_16816(acc[1][2 * ntp],     a[1][0], a[1][1], a[1][2], a[1][3], b0, b1);
      mma_16816(acc[1][2 * ntp + 1], a[1][0], a[1][1], a[1][2], a[1][3], b2, b3);
    }
  }
}

static __device__ __forceinline__ void softmax4(float l0, float l1, float l2, float l3, float* g) {
  float m = fmaxf(fmaxf(l0, l1), fmaxf(l2, l3));
  g[0] = __expf(l0 - m); g[1] = __expf(l1 - m); g[2] = __expf(l2 - m); g[3] = __expf(l3 - m);
  float inv = 1.0f / (g[0] + g[1] + g[2] + g[3]);
  g[0] *= inv; g[1] *= inv; g[2] *= inv; g[3] *= inv;
}

__global__ void __launch_bounds__(TPB, 1)
moe2_kernel(const float* __restrict__ x,
            const float* __restrict__ wgA, const float* __restrict__ weA, const float* __restrict__ beA,
            const float* __restrict__ wgB, const float* __restrict__ weB, const float* __restrict__ beB,
            float* __restrict__ out)
{
  extern __shared__ char smemRaw[];
  Smem& s = *reinterpret_cast<Smem*>(smemRaw);
  const int tid  = threadIdx.x;
  const int lane = tid & 31;
  const int warp = tid >> 5;
  const long long tok0 = (long long)blockIdx.x * TOK;

  // ---- Stage weights (W' layout: row k = e*64+d, col f). flat w_exp idx = k*64+f. ----
  for (int i = tid; i < 256 * 64; i += TPB) {
    int k = i >> 6, f = i & 63;
    s.Wa[k * WP + f] = __float2bfloat16(weA[i]);
    s.Wb[k * WP + f] = __float2bfloat16(weB[i]);
  }
  s.wga[tid] = wgA[tid];   // 64*4 = 256 elems
  s.wgb[tid] = wgB[tid];
  __syncthreads();

  // ---- c_e = b_e @ W_e (tiny; b is zeros in this dataset but handled for generality) ----
  {
    int kbase = (tid >> 6) * 64;     // e*64
    int f = tid & 63;
    float sa = 0.f, sb = 0.f;
    #pragma unroll 8
    for (int d = 0; d < 64; d++) {
      sa += beA[kbase + d] * __bfloat162float(s.Wa[(kbase + d) * WP + f]);
      sb += beB[kbase + d] * __bfloat162float(s.Wb[(kbase + d) * WP + f]);
    }
    s.ca[tid] = sa;
    s.cb[tid] = sb;
  }

  // ---- Layer A gates: thread t handles token t (fp32 from gmem) ----
  {
    const float4* xr = reinterpret_cast<const float4*>(x + (tok0 + tid) * 64);
    float l0 = 0.f, l1 = 0.f, l2 = 0.f, l3 = 0.f;
    #pragma unroll
    for (int i = 0; i < 16; i++) {
      float4 v = xr[i];
      int d = 4 * i;
      l0 += v.x * s.wga[d*4+0] + v.y * s.wga[(d+1)*4+0] + v.z * s.wga[(d+2)*4+0] + v.w * s.wga[(d+3)*4+0];
      l1 += v.x * s.wga[d*4+1] + v.y * s.wga[(d+1)*4+1] + v.z * s.wga[(d+2)*4+1] + v.w * s.wga[(d+3)*4+1];
      l2 += v.x * s.wga[d*4+2] + v.y * s.wga[(d+1)*4+2] + v.z * s.wga[(d+2)*4+2] + v.w * s.wga[(d+3)*4+2];
      l3 += v.x * s.wga[d*4+3] + v.y * s.wga[(d+1)*4+3] + v.z * s.wga[(d+2)*4+3] + v.w * s.wga[(d+3)*4+3];
    }
    float g[4];
    softmax4(l0, l1, l2, l3, g);
    s.gates[tid * 4 + 0] = g[0]; s.gates[tid * 4 + 1] = g[1];
    s.gates[tid * 4 + 2] = g[2]; s.gates[tid * 4 + 3] = g[3];
  }
  __syncthreads();

  // ---- Build A' = gate-scaled x copies (warp-per-row: coalesced gmem, conflict-free smem) ----
  {
    const float2* x2 = reinterpret_cast<const float2*>(x);
    #pragma unroll 4
    for (int it = 0; it < (TOK * 32) / TPB; it++) {
      int p = tid + it * TPB;
      int t = p >> 5, dp = p & 31;           // all 32 lanes: same token row, consecutive dp
      float2 v = x2[(tok0 + t) * 32 + dp];
      float g0 = s.gates[t*4+0], g1 = s.gates[t*4+1], g2 = s.gates[t*4+2], g3 = s.gates[t*4+3];
      __nv_bfloat162* row = reinterpret_cast<__nv_bfloat162*>(&s.Ap[t * APP]);
      row[0*32 + dp] = __floats2bfloat162_rn(g0 * v.x, g0 * v.y);
      row[1*32 + dp] = __floats2bfloat162_rn(g1 * v.x, g1 * v.y);
      row[2*32 + dp] = __floats2bfloat162_rn(g2 * v.x, g2 * v.y);
      row[3*32 + dp] = __floats2bfloat162_rn(g3 * v.x, g3 * v.y);
    }
  }
  __syncthreads();

  // ---- GEMM A ----
  float acc[2][8][4];
  #pragma unroll
  for (int mt = 0; mt < 2; mt++)
    #pragma unroll
    for (int nt = 0; nt < 8; nt++)
      #pragma unroll
      for (int r = 0; r < 4; r++) acc[mt][nt][r] = 0.f;
  gemm256(s.Ap, s.Wa, acc, warp, lane);
  __syncthreads();   // everyone done reading A' before we overwrite its first 64 cols

  // ---- Epilogue A: h = acc - sum_e g_e*c_a  -> bf16 into Ap[:,0:64] ----
  {
    const int g4 = lane >> 2;
    const int q2 = (lane & 3) * 2;
    #pragma unroll
    for (int mt = 0; mt < 2; mt++) {
      int r0 = warp * 32 + mt * 16 + g4;
      int r1 = r0 + 8;
      float gr0[4], gr1[4];
      #pragma unroll
      for (int e = 0; e < 4; e++) { gr0[e] = s.gates[r0*4+e]; gr1[e] = s.gates[r1*4+e]; }
      #pragma unroll
      for (int nt = 0; nt < 8; nt++) {
        int col = nt * 8 + q2;
        float c0 = 0.f, c1 = 0.f, c2 = 0.f, c3 = 0.f;
        #pragma unroll
        for (int e = 0; e < 4; e++) {
          float ce0 = s.ca[e*64 + col], ce1 = s.ca[e*64 + col + 1];
          c0 += gr0[e] * ce0; c1 += gr0[e] * ce1;
          c2 += gr1[e] * ce0; c3 += gr1[e] * ce1;
        }
        *reinterpret_cast<__nv_bfloat162*>(&s.Ap[r0 * APP + col]) =
            __floats2bfloat162_rn(acc[mt][nt][0] - c0, acc[mt][nt][1] - c1);
        *reinterpret_cast<__nv_bfloat162*>(&s.Ap[r1 * APP + col]) =
            __floats2bfloat162_rn(acc[mt][nt][2] - c2, acc[mt][nt][3] - c3);
      }
    }
  }
  __syncthreads();

  // ---- Layer B gates from h (bf16 in smem) ----
  {
    const __nv_bfloat162* row = reinterpret_cast<const __nv_bfloat162*>(&s.Ap[tid * APP]);
    float l0 = 0.f, l1 = 0.f, l2 = 0.f, l3 = 0.f;
    #pragma unroll
    for (int dp = 0; dp < 32; dp++) {
      __nv_bfloat162 p = row[dp];
      float hx = __bfloat162float(p.x), hy = __bfloat162float(p.y);
      int d = 2 * dp;
      l0 += hx * s.wgb[d*4+0] + hy * s.wgb[(d+1)*4+0];
      l1 += hx * s.wgb[d*4+1] + hy * s.wgb[(d+1)*4+1];
      l2 += hx * s.wgb[d*4+2] + hy * s.wgb[(d+1)*4+2];
      l3 += hx * s.wgb[d*4+3] + hy * s.wgb[(d+1)*4+3];
    }
    float g[4];
    softmax4(l0, l1, l2, l3, g);
    s.gates[tid * 4 + 0] = g[0]; s.gates[tid * 4 + 1] = g[1];
    s.gates[tid * 4 + 2] = g[2]; s.gates[tid * 4 + 3] = g[3];
  }
  __syncthreads();

  // ---- Expand A' in place: [g_e * h] for e=0..3 (e=0 overwrites h last, after reg load) ----
  {
    #pragma unroll 4
    for (int it = 0; it < (TOK * 32) / TPB; it++) {
      int p = tid + it * TPB;
      int t = p >> 5, dp = p & 31;
      __nv_bfloat162* row = reinterpret_cast<__nv_bfloat162*>(&s.Ap[t * APP]);
      __nv_bfloat162 hp = row[dp];
      float hx = __bfloat162float(hp.x), hy = __bfloat162float(hp.y);
      float g0 = s.gates[t*4+0], g1 = s.gates[t*4+1], g2 = s.gates[t*4+2], g3 = s.gates[t*4+3];
      row[3*32 + dp] = __floats2bfloat162_rn(g3 * hx, g3 * hy);
      row[2*32 + dp] = __floats2bfloat162_rn(g2 * hx, g2 * hy);
      row[1*32 + dp] = __floats2bfloat162_rn(g1 * hx, g1 * hy);
      row[0*32 + dp] = __floats2bfloat162_rn(g0 * hx, g0 * hy);
    }
  }
  __syncthreads();

  // ---- GEMM B ----
  #pragma unroll
  for (int mt = 0; mt < 2; mt++)
    #pragma unroll
    for (int nt = 0; nt < 8; nt++)
      #pragma unroll
      for (int r = 0; r < 4; r++) acc[mt][nt][r] = 0.f;
  gemm256(s.Ap, s.Wb, acc, warp, lane);

  // ---- Epilogue B: out = acc - sum_e g_e*c_b + x (fp32 residual from gmem) ----
  {
    const int g4 = lane >> 2;
    const int q2 = (lane & 3) * 2;
    #pragma unroll
    for (int mt = 0; mt < 2; mt++) {
      int r0 = warp * 32 + mt * 16 + g4;
      int r1 = r0 + 8;
      float gr0[4], gr1[4];
      #pragma unroll
      for (int e = 0; e < 4; e++) { gr0[e] = s.gates[r0*4+e]; gr1[e] = s.gates[r1*4+e]; }
      long long gr0g = (tok0 + r0) * 64;
      long long gr1g = (tok0 + r1) * 64;
      #pragma unroll
      for (int nt = 0; nt < 8; nt++) {
        int col = nt * 8 + q2;
        float c0 = 0.f, c1 = 0.f, c2 = 0.f, c3 = 0.f;
        #pragma unroll
        for (int e = 0; e < 4; e++) {
          float ce0 = s.cb[e*64 + col], ce1 = s.cb[e*64 + col + 1];
          c0 += gr0[e] * ce0; c1 += gr0[e] * ce1;
          c2 += gr1[e] * ce0; c3 += gr1[e] * ce1;
        }
        float2 xr0 = *reinterpret_cast<const float2*>(&x[gr0g + col]);
        float2 xr1 = *reinterpret_cast<const float2*>(&x[gr1g + col]);
        float2 o0 = make_float2(acc[mt][nt][0] - c0 + xr0.x, acc[mt][nt][1] - c1 + xr0.y);
        float2 o1 = make_float2(acc[mt][nt][2] - c2 + xr1.x, acc[mt][nt][3] - c3 + xr1.y);
        *reinterpret_cast<float2*>(&out[gr0g + col]) = o0;
        *reinterpret_cast<float2*>(&out[gr1g + col]) = o1;
      }
    }
  }
}

extern "C" void kernel_launch(void* const* d_in, const int* in_sizes, int n_in,
                              void* d_out, int out_size) {
  const float* x   = (const float*)d_in[0];
  const float* wgA = (const float*)d_in[1];
  const float* weA = (const float*)d_in[2];
  const float* beA = (const float*)d_in[3];
  const float* wgB = (const float*)d_in[4];
  const float* weB = (const float*)d_in[5];
  const float* beB = (const float*)d_in[6];
  float* out = (float*)d_out;

  int nTok   = in_sizes[0] / 64;
  int blocks = nTok / TOK;                 // 524288/256 = 2048
  size_t smem = sizeof(Smem);              // ~217 KB -> opt-in

  cudaFuncSetAttribute(moe2_kernel, cudaFuncAttributeMaxDynamicSharedMemorySize, (int)smem);
  moe2_kernel<<<blocks, TPB, smem>>>(x, wgA, weA, beA, wgB, weB, beB, out);
}

// round 4
// speedup vs baseline: 1.4635x; 1.4635x over previous
#include <cuda_runtime.h>
#include <cuda_bf16.h>
#include <stdint.h>

#define TPB 256
#define TOK 128          // tokens per CTA
#define AP  72           // A pitch in bf16 elems (36 words; 36%32==4 -> ldmatrix conflict-free)
#define WPITCH 72        // W pitch in bf16 elems

// Preprocessed weights (written by prep_kernel, read by main kernel)
__device__ __nv_bfloat16 g_W[2][256 * WPITCH];  // [layer][(e*64+d)*72 + f]
__device__ float g_c[2][256];                    // c[e*64+f] = (b_e @ W_e)[f]
__device__ float g_wg[2][256];                   // gate weights [d*4+e]

// ---------------------------------------------------------------------------
__global__ void prep_kernel(const float* __restrict__ wgA, const float* __restrict__ weA,
                            const float* __restrict__ beA,
                            const float* __restrict__ wgB, const float* __restrict__ weB,
                            const float* __restrict__ beB) {
  int idx = blockIdx.x * blockDim.x + threadIdx.x;
  int stride = gridDim.x * blockDim.x;
  // bf16-convert expert weights into padded layout
  for (int i = idx; i < 2 * 256 * 64; i += stride) {
    int l = i >> 14; int r = i & 16383; int k = r >> 6, f = r & 63;
    const float* we = l ? weB : weA;
    g_W[l][k * WPITCH + f] = __float2bfloat16(we[r]);
  }
  // gate weights
  for (int i = idx; i < 512; i += stride) {
    int l = i >> 8; int r = i & 255;
    g_wg[l][r] = l ? wgB[r] : wgA[r];
  }
  // bias correction c_e = b_e @ W_e
  for (int i = idx; i < 512; i += stride) {
    int l = i >> 8; int r = i & 255;
    const float* be = l ? beB : beA;
    const float* we = l ? weB : weA;
    int e = r >> 6, f = r & 63;
    float s = 0.f;
    #pragma unroll 8
    for (int d = 0; d < 64; d++) s += be[e * 64 + d] * we[e * 4096 + d * 64 + f];
    g_c[l][r] = s;
  }
}

// ---------------------------------------------------------------------------
struct Smem {
  __nv_bfloat16 Ap[TOK * AP];        // activation tile (x, later h), bf16
  __nv_bfloat16 W[2][256 * WPITCH];  // both layers' weights
  float gatesA[TOK * 4];
};

static __device__ __forceinline__ void ldm_x4(uint32_t addr, uint32_t& r0, uint32_t& r1,
                                              uint32_t& r2, uint32_t& r3) {
  asm volatile("ldmatrix.sync.aligned.m8n8.x4.shared.b16 {%0,%1,%2,%3}, [%4];"
               : "=r"(r0), "=r"(r1), "=r"(r2), "=r"(r3) : "r"(addr));
}
static __device__ __forceinline__ void ldm_x4_t(uint32_t addr, uint32_t& r0, uint32_t& r1,
                                                uint32_t& r2, uint32_t& r3) {
  asm volatile("ldmatrix.sync.aligned.m8n8.x4.trans.shared.b16 {%0,%1,%2,%3}, [%4];"
               : "=r"(r0), "=r"(r1), "=r"(r2), "=r"(r3) : "r"(addr));
}
static __device__ __forceinline__ void mma_16816(float* c,
                                                 uint32_t a0, uint32_t a1, uint32_t a2, uint32_t a3,
                                                 uint32_t b0, uint32_t b1) {
  asm volatile("mma.sync.aligned.m16n8k16.row.col.f32.bf16.bf16.f32 "
               "{%0,%1,%2,%3},{%4,%5,%6,%7},{%8,%9},{%0,%1,%2,%3};"
               : "+f"(c[0]), "+f"(c[1]), "+f"(c[2]), "+f"(c[3])
               : "r"(a0), "r"(a1), "r"(a2), "r"(a3), "r"(b0), "r"(b1));
}

static __device__ __forceinline__ uint32_t scale2(uint32_t a, __nv_bfloat162 s) {
  __nv_bfloat162 v = __hmul2(*reinterpret_cast<__nv_bfloat162*>(&a), s);
  return *reinterpret_cast<uint32_t*>(&v);
}

static __device__ __forceinline__ void softmax4(const float* l, float* g) {
  float m = fmaxf(fmaxf(l[0], l[1]), fmaxf(l[2], l[3]));
  g[0] = __expf(l[0] - m); g[1] = __expf(l[1] - m);
  g[2] = __expf(l[2] - m); g[3] = __expf(l[3] - m);
  float inv = 1.0f / (g[0] + g[1] + g[2] + g[3]);
  g[0] *= inv; g[1] *= inv; g[2] *= inv; g[3] *= inv;
}

// Per-warp gated GEMM: acc[nt][j] += sum_e g_row[e] * (A_rows @ W_e)
// A frags (16 rows x K=64) are pre-loaded; gate folded into bf16 A-frags.
static __device__ __forceinline__ void gemm_gated(const uint32_t a[4][4], uint32_t wBase,
                                                  const float g0[4], const float g1[4],
                                                  float acc[8][4], int lane) {
  const int bk = (lane & 7) + ((lane >> 3) & 1) * 8;
  const int bn = (lane >> 4) * 8;
  #pragma unroll
  for (int e = 0; e < 4; e++) {
    __nv_bfloat162 s0 = __float2bfloat162_rn(g0[e]);
    __nv_bfloat162 s1 = __float2bfloat162_rn(g1[e]);
    #pragma unroll
    for (int ks = 0; ks < 4; ks++) {
      uint32_t sa0 = scale2(a[ks][0], s0);
      uint32_t sa1 = scale2(a[ks][1], s1);
      uint32_t sa2 = scale2(a[ks][2], s0);
      uint32_t sa3 = scale2(a[ks][3], s1);
      uint32_t rowK = (uint32_t)(e * 64 + ks * 16 + bk);
      #pragma unroll
      for (int ntp = 0; ntp < 4; ntp++) {
        uint32_t b0, b1, b2, b3;
        ldm_x4_t(wBase + 2u * (rowK * WPITCH + ntp * 16 + bn), b0, b1, b2, b3);
        mma_16816(acc[2 * ntp],     sa0, sa1, sa2, sa3, b0, b1);
        mma_16816(acc[2 * ntp + 1], sa0, sa1, sa2, sa3, b2, b3);
      }
    }
  }
}

// ---------------------------------------------------------------------------
__global__ void __launch_bounds__(TPB, 2)
moe2_kernel(const float* __restrict__ x, float* __restrict__ out)
{
  extern __shared__ char smemRaw[];
  Smem& s = *reinterpret_cast<Smem*>(smemRaw);
  const int tid  = threadIdx.x;
  const int lane = tid & 31;
  const int warp = tid >> 5;
  const long long tok0 = (long long)blockIdx.x * TOK;

  // ===== Phase 1 (single barrier): stage weights, x tile, gates A =====
  {
    int4* dstW = reinterpret_cast<int4*>(s.W[0]);
    const int4* srcW = reinterpret_cast<const int4*>(g_W[0]);
    #pragma unroll
    for (int it = 0; it < (2 * 256 * WPITCH * 2) / (16 * TPB); it++)
      dstW[tid + it * TPB] = srcW[tid + it * TPB];
  }
  {
    // x -> smem bf16: warp-per-row (coalesced gmem, conflict-free smem)
    const float2* x2 = reinterpret_cast<const float2*>(x);
    __nv_bfloat162* Ap2 = reinterpret_cast<__nv_bfloat162*>(s.Ap);
    #pragma unroll
    for (int it = 0; it < (TOK * 32) / TPB; it++) {
      int p = tid + it * TPB;
      int t = p >> 5, dp = p & 31;
      float2 v = x2[(tok0 + t) * 32 + dp];
      Ap2[t * (AP / 2) + dp] = __floats2bfloat162_rn(v.x, v.y);
    }
  }
  if (tid < TOK) {
    // gates A from fp32 x (gmem, L1/L2-hot) and g_wg (L1 broadcast)
    const float4* xr  = reinterpret_cast<const float4*>(x + (tok0 + tid) * 64);
    const float4* wg4 = reinterpret_cast<const float4*>(g_wg[0]);
    float l[4] = {0.f, 0.f, 0.f, 0.f};
    #pragma unroll
    for (int i = 0; i < 16; i++) {
      float4 v = xr[i];
      float4 w0 = wg4[4 * i], w1 = wg4[4 * i + 1], w2 = wg4[4 * i + 2], w3 = wg4[4 * i + 3];
      l[0] += v.x * w0.x + v.y * w1.x + v.z * w2.x + v.w * w3.x;
      l[1] += v.x * w0.y + v.y * w1.y + v.z * w2.y + v.w * w3.y;
      l[2] += v.x * w0.z + v.y * w1.z + v.z * w2.z + v.w * w3.z;
      l[3] += v.x * w0.w + v.y * w1.w + v.z * w2.w + v.w * w3.w;
    }
    float g[4];
    softmax4(l, g);
    s.gatesA[tid * 4 + 0] = g[0]; s.gatesA[tid * 4 + 1] = g[1];
    s.gatesA[tid * 4 + 2] = g[2]; s.gatesA[tid * 4 + 3] = g[3];
  }
  __syncthreads();
  // ===== From here on: warps fully independent (each owns 16 token rows) =====

  const int m0 = warp * 16;
  const int r0 = m0 + (lane >> 2);       // C-frag row 0 (local)
  const int r1 = r0 + 8;                 // C-frag row 1
  const int q2 = (lane & 3) * 2;         // C-frag col offset within n8 tile
  uint32_t apBase = (uint32_t)__cvta_generic_to_shared(s.Ap);
  uint32_t waBase = (uint32_t)__cvta_generic_to_shared(s.W[0]);
  uint32_t wbBase = (uint32_t)__cvta_generic_to_shared(s.W[1]);
  const int arow  = lane & 15;
  const int acolh = (lane >> 4) * 8;

  // Load A fragments (x) for this warp's 16 rows, K=64
  uint32_t a[4][4];
  #pragma unroll
  for (int ks = 0; ks < 4; ks++)
    ldm_x4(apBase + 2u * (uint32_t)((m0 + arow) * AP + ks * 16 + acolh),
           a[ks][0], a[ks][1], a[ks][2], a[ks][3]);

  // Gates A for this warp's two frag rows
  float gA0[4], gA1[4];
  #pragma unroll
  for (int e = 0; e < 4; e++) {
    gA0[e] = s.gatesA[r0 * 4 + e];
    gA1[e] = s.gatesA[r1 * 4 + e];
  }

  // ===== Layer A GEMM =====
  float acc[8][4];
  #pragma unroll
  for (int nt = 0; nt < 8; nt++)
    #pragma unroll
    for (int j = 0; j < 4; j++) acc[nt][j] = 0.f;
  gemm_gated(a, waBase, gA0, gA1, acc, lane);

  // Bias correction: acc -= sum_e g_e * c_a[e][col]
  {
    const float* cL = g_c[0];
    #pragma unroll
    for (int nt = 0; nt < 8; nt++) {
      int col = nt * 8 + q2;
      float c00 = 0.f, c01 = 0.f, c10 = 0.f, c11 = 0.f;
      #pragma unroll
      for (int e = 0; e < 4; e++) {
        float2 cv = *reinterpret_cast<const float2*>(&cL[e * 64 + col]);
        c00 += gA0[e] * cv.x; c01 += gA0[e] * cv.y;
        c10 += gA1[e] * cv.x; c11 += gA1[e] * cv.y;
      }
      acc[nt][0] -= c00; acc[nt][1] -= c01; acc[nt][2] -= c10; acc[nt][3] -= c11;
    }
  }

  // ===== Gates B: in-register partial dots + shfl reduce over the 4-lane row group =====
  float gB0[4], gB1[4];
  {
    const float* wgb = g_wg[1];
    float l0[4] = {0.f, 0.f, 0.f, 0.f}, l1[4] = {0.f, 0.f, 0.f, 0.f};
    #pragma unroll
    for (int nt = 0; nt < 8; nt++) {
      int col = nt * 8 + q2;
      float4 w0 = *reinterpret_cast<const float4*>(&wgb[col * 4]);
      float4 w1 = *reinterpret_cast<const float4*>(&wgb[(col + 1) * 4]);
      l0[0] += acc[nt][0] * w0.x + acc[nt][1] * w1.x;
      l0[1] += acc[nt][0] * w0.y + acc[nt][1] * w1.y;
      l0[2] += acc[nt][0] * w0.z + acc[nt][1] * w1.z;
      l0[3] += acc[nt][0] * w0.w + acc[nt][1] * w1.w;
      l1[0] += acc[nt][2] * w0.x + acc[nt][3] * w1.x;
      l1[1] += acc[nt][2] * w0.y + acc[nt][3] * w1.y;
      l1[2] += acc[nt][2] * w0.z + acc[nt][3] * w1.z;
      l1[3] += acc[nt][2] * w0.w + acc[nt][3] * w1.w;
    }
    #pragma unroll
    for (int e = 0; e < 4; e++) {
      l0[e] += __shfl_xor_sync(0xffffffffu, l0[e], 1);
      l0[e] += __shfl_xor_sync(0xffffffffu, l0[e], 2);
      l1[e] += __shfl_xor_sync(0xffffffffu, l1[e], 1);
      l1[e] += __shfl_xor_sync(0xffffffffu, l1[e], 2);
    }
    softmax4(l0, gB0);
    softmax4(l1, gB1);
  }

  // ===== h -> smem bf16 (own rows only), reload as A fragments =====
  #pragma unroll
  for (int nt = 0; nt < 8; nt++) {
    int col = nt * 8 + q2;
    *reinterpret_cast<__nv_bfloat162*>(&s.Ap[r0 * AP + col]) =
        __floats2bfloat162_rn(acc[nt][0], acc[nt][1]);
    *reinterpret_cast<__nv_bfloat162*>(&s.Ap[r1 * AP + col]) =
        __floats2bfloat162_rn(acc[nt][2], acc[nt][3]);
  }
  __syncwarp();
  #pragma unroll
  for (int ks = 0; ks < 4; ks++)
    ldm_x4(apBase + 2u * (uint32_t)((m0 + arow) * AP + ks * 16 + acolh),
           a[ks][0], a[ks][1], a[ks][2], a[ks][3]);

  // ===== Layer B GEMM =====
  #pragma unroll
  for (int nt = 0; nt < 8; nt++)
    #pragma unroll
    for (int j = 0; j < 4; j++) acc[nt][j] = 0.f;
  gemm_gated(a, wbBase, gB0, gB1, acc, lane);

  // ===== Epilogue: bias correction + fp32 residual + store =====
  {
    const float* cL = g_c[1];
    long long gr0 = (tok0 + r0) * 64;
    long long gr1 = (tok0 + r1) * 64;
    #pragma unroll
    for (int nt = 0; nt < 8; nt++) {
      int col = nt * 8 + q2;
      float c00 = 0.f, c01 = 0.f, c10 = 0.f, c11 = 0.f;
      #pragma unroll
      for (int e = 0; e < 4; e++) {
        float2 cv = *reinterpret_cast<const float2*>(&cL[e * 64 + col]);
        c00 += gB0[e] * cv.x; c01 += gB0[e] * cv.y;
        c10 += gB1[e] * cv.x; c11 += gB1[e] * cv.y;
      }
      float2 xr0 = *reinterpret_cast<const float2*>(&x[gr0 + col]);
      float2 xr1 = *reinterpret_cast<const float2*>(&x[gr1 + col]);
      float2 o0 = make_float2(acc[nt][0] - c00 + xr0.x, acc[nt][1] - c01 + xr0.y);
      float2 o1 = make_float2(acc[nt][2] - c10 + xr1.x, acc[nt][3] - c11 + xr1.y);
      *reinterpret_cast<float2*>(&out[gr0 + col]) = o0;
      *reinterpret_cast<float2*>(&out[gr1 + col]) = o1;
    }
  }
}

// ---------------------------------------------------------------------------
extern "C" void kernel_launch(void* const* d_in, const int* in_sizes, int n_in,
                              void* d_out, int out_size) {
  const float* x   = (const float*)d_in[0];
  const float* wgA = (const float*)d_in[1];
  const float* weA = (const float*)d_in[2];
  const float* beA = (const float*)d_in[3];
  const float* wgB = (const float*)d_in[4];
  const float* weB = (const float*)d_in[5];
  const float* beB = (const float*)d_in[6];
  float* out = (float*)d_out;

  prep_kernel<<<64, 256>>>(wgA, weA, beA, wgB, weB, beB);

  int nTok   = in_sizes[0] / 64;
  int blocks = nTok / TOK;                 // 524288/128 = 4096
  size_t smem = sizeof(Smem);              // ~92 KB -> 2 CTAs/SM

  cudaFuncSetAttribute(moe2_kernel, cudaFuncAttributeMaxDynamicSharedMemorySize, (int)smem);
  moe2_kernel<<<blocks, TPB, smem>>>(x, out);
}

// round 9
// speedup vs baseline: 1.6019x; 1.0946x over previous
#include <cuda_runtime.h>
#include <cuda_bf16.h>
#include <stdint.h>

#define TPB 128
#define TOK 128          // tokens per CTA
#define AP  72           // A pitch in bf16 elems (36 words; 36%32==4 -> ldmatrix conflict-free)
#define WPITCH 72        // W pitch in bf16 elems

// Preprocessed weights (written by prep_kernel, read by main kernel)
__device__ __nv_bfloat16 g_W[2][256 * WPITCH];  // [layer][(e*64+d)*72 + f]
__device__ float g_c[2][256];                    // c[e*64+f] = (b_e @ W_e)[f]
__device__ float g_wg[2][256];                   // gate weights [d*4+e]

// ---------------------------------------------------------------------------
__global__ void prep_kernel(const float* __restrict__ wgA, const float* __restrict__ weA,
                            const float* __restrict__ beA,
                            const float* __restrict__ wgB, const float* __restrict__ weB,
                            const float* __restrict__ beB) {
  int idx = blockIdx.x * blockDim.x + threadIdx.x;
  int stride = gridDim.x * blockDim.x;
  for (int i = idx; i < 2 * 256 * 64; i += stride) {
    int l = i >> 14; int r = i & 16383; int k = r >> 6, f = r & 63;
    const float* we = l ? weB : weA;
    g_W[l][k * WPITCH + f] = __float2bfloat16(we[r]);
  }
  for (int i = idx; i < 512; i += stride) {
    int l = i >> 8; int r = i & 255;
    g_wg[l][r] = l ? wgB[r] : wgA[r];
  }
  for (int i = idx; i < 512; i += stride) {
    int l = i >> 8; int r = i & 255;
    const float* be = l ? beB : beA;
    const float* we = l ? weB : weA;
    int e = r >> 6, f = r & 63;
    float s = 0.f;
    #pragma unroll 8
    for (int d = 0; d < 64; d++) s += be[e * 64 + d] * we[e * 4096 + d * 64 + f];
    g_c[l][r] = s;
  }
}

// ---------------------------------------------------------------------------
struct Smem {
  __nv_bfloat16 Ap[TOK * AP];        // activation tile (x, later h), bf16
  __nv_bfloat16 W[2][256 * WPITCH];  // both layers' weights
  float gatesA[TOK * 4];
};

static __device__ __forceinline__ void ldm_x4(uint32_t addr, uint32_t& r0, uint32_t& r1,
                                              uint32_t& r2, uint32_t& r3) {
  asm volatile("ldmatrix.sync.aligned.m8n8.x4.shared.b16 {%0,%1,%2,%3}, [%4];"
               : "=r"(r0), "=r"(r1), "=r"(r2), "=r"(r3) : "r"(addr));
}
static __device__ __forceinline__ void ldm_x4_t(uint32_t addr, uint32_t& r0, uint32_t& r1,
                                                uint32_t& r2, uint32_t& r3) {
  asm volatile("ldmatrix.sync.aligned.m8n8.x4.trans.shared.b16 {%0,%1,%2,%3}, [%4];"
               : "=r"(r0), "=r"(r1), "=r"(r2), "=r"(r3) : "r"(addr));
}
static __device__ __forceinline__ void mma_16816(float* c,
                                                 uint32_t a0, uint32_t a1, uint32_t a2, uint32_t a3,
                                                 uint32_t b0, uint32_t b1) {
  asm volatile("mma.sync.aligned.m16n8k16.row.col.f32.bf16.bf16.f32 "
               "{%0,%1,%2,%3},{%4,%5,%6,%7},{%8,%9},{%0,%1,%2,%3};"
               : "+f"(c[0]), "+f"(c[1]), "+f"(c[2]), "+f"(c[3])
               : "r"(a0), "r"(a1), "r"(a2), "r"(a3), "r"(b0), "r"(b1));
}

static __device__ __forceinline__ uint32_t scale2(uint32_t a, __nv_bfloat162 s) {
  __nv_bfloat162 v = __hmul2(*reinterpret_cast<__nv_bfloat162*>(&a), s);
  return *reinterpret_cast<uint32_t*>(&v);
}

static __device__ __forceinline__ void softmax4(const float* l, float* g) {
  float m = fmaxf(fmaxf(l[0], l[1]), fmaxf(l[2], l[3]));
  g[0] = __expf(l[0] - m); g[1] = __expf(l[1] - m);
  g[2] = __expf(l[2] - m); g[3] = __expf(l[3] - m);
  float inv = 1.0f / (g[0] + g[1] + g[2] + g[3]);
  g[0] *= inv; g[1] *= inv; g[2] *= inv; g[3] *= inv;
}

// Per-warp gated GEMM over M=32 (two m16 tiles sharing every B fragment).
// acc[mt][nt][j] += sum_e g[mt][row][e] * (A_rows @ W_e); gate folded into bf16 A-frags.
static __device__ __forceinline__ void gemm_gated2(const uint32_t a[2][4][4], uint32_t wBase,
                                                   const float g[2][2][4],
                                                   float acc[2][8][4], int lane) {
  const int bk = (lane & 7) + ((lane >> 3) & 1) * 8;
  const int bn = (lane >> 4) * 8;
  #pragma unroll
  for (int e = 0; e < 4; e++) {
    __nv_bfloat162 s00 = __float2bfloat162_rn(g[0][0][e]);
    __nv_bfloat162 s01 = __float2bfloat162_rn(g[0][1][e]);
    __nv_bfloat162 s10 = __float2bfloat162_rn(g[1][0][e]);
    __nv_bfloat162 s11 = __float2bfloat162_rn(g[1][1][e]);
    #pragma unroll
    for (int ks = 0; ks < 4; ks++) {
      uint32_t sa[2][4];
      sa[0][0] = scale2(a[0][ks][0], s00);
      sa[0][1] = scale2(a[0][ks][1], s01);
      sa[0][2] = scale2(a[0][ks][2], s00);
      sa[0][3] = scale2(a[0][ks][3], s01);
      sa[1][0] = scale2(a[1][ks][0], s10);
      sa[1][1] = scale2(a[1][ks][1], s11);
      sa[1][2] = scale2(a[1][ks][2], s10);
      sa[1][3] = scale2(a[1][ks][3], s11);
      uint32_t rowK = (uint32_t)(e * 64 + ks * 16 + bk);
      #pragma unroll
      for (int ntp = 0; ntp < 4; ntp++) {
        uint32_t b0, b1, b2, b3;
        ldm_x4_t(wBase + 2u * (rowK * WPITCH + ntp * 16 + bn), b0, b1, b2, b3);
        mma_16816(acc[0][2 * ntp],     sa[0][0], sa[0][1], sa[0][2], sa[0][3], b0, b1);
        mma_16816(acc[1][2 * ntp],     sa[1][0], sa[1][1], sa[1][2], sa[1][3], b0, b1);
        mma_16816(acc[0][2 * ntp + 1], sa[0][0], sa[0][1], sa[0][2], sa[0][3], b2, b3);
        mma_16816(acc[1][2 * ntp + 1], sa[1][0], sa[1][1], sa[1][2], sa[1][3], b2, b3);
      }
    }
  }
}

// ---------------------------------------------------------------------------
__global__ void __launch_bounds__(TPB, 2)
moe2_kernel(const float* __restrict__ x, float* __restrict__ out)
{
  extern __shared__ char smemRaw[];
  Smem& s = *reinterpret_cast<Smem*>(smemRaw);
  const int tid  = threadIdx.x;
  const int lane = tid & 31;
  const int warp = tid >> 5;
  const long long tok0 = (long long)blockIdx.x * TOK;

  // ===== Phase 1 (single barrier): stage weights, x tile, gates A =====
  {
    int4* dstW = reinterpret_cast<int4*>(s.W[0]);
    const int4* srcW = reinterpret_cast<const int4*>(g_W[0]);
    #pragma unroll
    for (int it = 0; it < (2 * 256 * WPITCH * 2) / (16 * TPB); it++)
      dstW[tid + it * TPB] = srcW[tid + it * TPB];
  }
  {
    // x -> smem bf16: warp-per-row (coalesced gmem, conflict-free smem)
    const float2* x2 = reinterpret_cast<const float2*>(x);
    __nv_bfloat162* Ap2 = reinterpret_cast<__nv_bfloat162*>(s.Ap);
    #pragma unroll
    for (int it = 0; it < (TOK * 32) / TPB; it++) {
      int p = tid + it * TPB;
      int t = p >> 5, dp = p & 31;
      float2 v = x2[(tok0 + t) * 32 + dp];
      Ap2[t * (AP / 2) + dp] = __floats2bfloat162_rn(v.x, v.y);
    }
  }
  {
    // gates A: thread t handles token t (TPB == TOK)
    const float4* xr  = reinterpret_cast<const float4*>(x + (tok0 + tid) * 64);
    const float4* wg4 = reinterpret_cast<const float4*>(g_wg[0]);
    float l[4] = {0.f, 0.f, 0.f, 0.f};
    #pragma unroll
    for (int i = 0; i < 16; i++) {
      float4 v = xr[i];
      float4 w0 = wg4[4 * i], w1 = wg4[4 * i + 1], w2 = wg4[4 * i + 2], w3 = wg4[4 * i + 3];
      l[0] += v.x * w0.x + v.y * w1.x + v.z * w2.x + v.w * w3.x;
      l[1] += v.x * w0.y + v.y * w1.y + v.z * w2.y + v.w * w3.y;
      l[2] += v.x * w0.z + v.y * w1.z + v.z * w2.z + v.w * w3.z;
      l[3] += v.x * w0.w + v.y * w1.w + v.z * w2.w + v.w * w3.w;
    }
    float g[4];
    softmax4(l, g);
    s.gatesA[tid * 4 + 0] = g[0]; s.gatesA[tid * 4 + 1] = g[1];
    s.gatesA[tid * 4 + 2] = g[2]; s.gatesA[tid * 4 + 3] = g[3];
  }
  __syncthreads();
  // ===== From here on: warps fully independent (each owns 32 token rows) =====

  const int m0 = warp * 32;
  const int g4 = lane >> 2;              // frag row within m8
  const int q2 = (lane & 3) * 2;         // frag col offset within n8 tile
  uint32_t apBase = (uint32_t)__cvta_generic_to_shared(s.Ap);
  uint32_t waBase = (uint32_t)__cvta_generic_to_shared(s.W[0]);
  uint32_t wbBase = (uint32_t)__cvta_generic_to_shared(s.W[1]);
  const int arow  = lane & 15;
  const int acolh = (lane >> 4) * 8;

  // Load A fragments (x) for this warp's 32 rows, K=64
  uint32_t a[2][4][4];
  #pragma unroll
  for (int mt = 0; mt < 2; mt++)
    #pragma unroll
    for (int ks = 0; ks < 4; ks++)
      ldm_x4(apBase + 2u * (uint32_t)((m0 + mt * 16 + arow) * AP + ks * 16 + acolh),
             a[mt][ks][0], a[mt][ks][1], a[mt][ks][2], a[mt][ks][3]);

  // Gates A for this warp's four frag rows: g[mt][half][e], rows m0+mt*16+{g4, g4+8}
  float gA[2][2][4];
  #pragma unroll
  for (int mt = 0; mt < 2; mt++)
    #pragma unroll
    for (int e = 0; e < 4; e++) {
      gA[mt][0][e] = s.gatesA[(m0 + mt * 16 + g4) * 4 + e];
      gA[mt][1][e] = s.gatesA[(m0 + mt * 16 + g4 + 8) * 4 + e];
    }

  // ===== Layer A GEMM =====
  float acc[2][8][4];
  #pragma unroll
  for (int mt = 0; mt < 2; mt++)
    #pragma unroll
    for (int nt = 0; nt < 8; nt++)
      #pragma unroll
      for (int j = 0; j < 4; j++) acc[mt][nt][j] = 0.f;
  gemm_gated2(a, waBase, gA, acc, lane);

  // Bias correction: acc -= sum_e g_e * c_a[e][col]
  {
    const float* cL = g_c[0];
    #pragma unroll
    for (int mt = 0; mt < 2; mt++)
      #pragma unroll
      for (int nt = 0; nt < 8; nt++) {
        int col = nt * 8 + q2;
        float c00 = 0.f, c01 = 0.f, c10 = 0.f, c11 = 0.f;
        #pragma unroll
        for (int e = 0; e < 4; e++) {
          float2 cv = *reinterpret_cast<const float2*>(&cL[e * 64 + col]);
          c00 += gA[mt][0][e] * cv.x; c01 += gA[mt][0][e] * cv.y;
          c10 += gA[mt][1][e] * cv.x; c11 += gA[mt][1][e] * cv.y;
        }
        acc[mt][nt][0] -= c00; acc[mt][nt][1] -= c01;
        acc[mt][nt][2] -= c10; acc[mt][nt][3] -= c11;
      }
  }

  // ===== Gates B: in-register partial dots + shfl reduce over the 4-lane row group =====
  float gB[2][2][4];
  {
    const float* wgb = g_wg[1];
    #pragma unroll
    for (int mt = 0; mt < 2; mt++) {
      float l0[4] = {0.f, 0.f, 0.f, 0.f}, l1[4] = {0.f, 0.f, 0.f, 0.f};
      #pragma unroll
      for (int nt = 0; nt < 8; nt++) {
        int col = nt * 8 + q2;
        float4 w0 = *reinterpret_cast<const float4*>(&wgb[col * 4]);
        float4 w1 = *reinterpret_cast<const float4*>(&wgb[(col + 1) * 4]);
        l0[0] += acc[mt][nt][0] * w0.x + acc[mt][nt][1] * w1.x;
        l0[1] += acc[mt][nt][0] * w0.y + acc[mt][nt][1] * w1.y;
        l0[2] += acc[mt][nt][0] * w0.z + acc[mt][nt][1] * w1.z;
        l0[3] += acc[mt][nt][0] * w0.w + acc[mt][nt][1] * w1.w;
        l1[0] += acc[mt][nt][2] * w0.x + acc[mt][nt][3] * w1.x;
        l1[1] += acc[mt][nt][2] * w0.y + acc[mt][nt][3] * w1.y;
        l1[2] += acc[mt][nt][2] * w0.z + acc[mt][nt][3] * w1.z;
        l1[3] += acc[mt][nt][2] * w0.w + acc[mt][nt][3] * w1.w;
      }
      #pragma unroll
      for (int e = 0; e < 4; e++) {
        l0[e] += __shfl_xor_sync(0xffffffffu, l0[e], 1);
        l0[e] += __shfl_xor_sync(0xffffffffu, l0[e], 2);
        l1[e] += __shfl_xor_sync(0xffffffffu, l1[e], 1);
        l1[e] += __shfl_xor_sync(0xffffffffu, l1[e], 2);
      }
      softmax4(l0, gB[mt][0]);
      softmax4(l1, gB[mt][1]);
    }
  }

  // ===== h -> smem bf16 (own rows only), reload as A fragments =====
  #pragma unroll
  for (int mt = 0; mt < 2; mt++) {
    int r0 = m0 + mt * 16 + g4;
    int r1 = r0 + 8;
    #pragma unroll
    for (int nt = 0; nt < 8; nt++) {
      int col = nt * 8 + q2;
      *reinterpret_cast<__nv_bfloat162*>(&s.Ap[r0 * AP + col]) =
          __floats2bfloat162_rn(acc[mt][nt][0], acc[mt][nt][1]);
      *reinterpret_cast<__nv_bfloat162*>(&s.Ap[r1 * AP + col]) =
          __floats2bfloat162_rn(acc[mt][nt][2], acc[mt][nt][3]);
    }
  }
  __syncwarp();
  #pragma unroll
  for (int mt = 0; mt < 2; mt++)
    #pragma unroll
    for (int ks = 0; ks < 4; ks++)
      ldm_x4(apBase + 2u * (uint32_t)((m0 + mt * 16 + arow) * AP + ks * 16 + acolh),
             a[mt][ks][0], a[mt][ks][1], a[mt][ks][2], a[mt][ks][3]);

  // ===== Layer B GEMM =====
  #pragma unroll
  for (int mt = 0; mt < 2; mt++)
    #pragma unroll
    for (int nt = 0; nt < 8; nt++)
      #pragma unroll
      for (int j = 0; j < 4; j++) acc[mt][nt][j] = 0.f;
  gemm_gated2(a, wbBase, gB, acc, lane);

  // ===== Epilogue: bias correction + fp32 residual + store =====
  {
    const float* cL = g_c[1];
    #pragma unroll
    for (int mt = 0; mt < 2; mt++) {
      int r0 = m0 + mt * 16 + g4;
      int r1 = r0 + 8;
      long long gr0 = (tok0 + r0) * 64;
      long long gr1 = (tok0 + r1) * 64;
      #pragma unroll
      for (int nt = 0; nt < 8; nt++) {
        int col = nt * 8 + q2;
        float c00 = 0.f, c01 = 0.f, c10 = 0.f, c11 = 0.f;
        #pragma unroll
        for (int e = 0; e < 4; e++) {
          float2 cv = *reinterpret_cast<const float2*>(&cL[e * 64 + col]);
          c00 += gB[mt][0][e] * cv.x; c01 += gB[mt][0][e] * cv.y;
          c10 += gB[mt][1][e] * cv.x; c11 += gB[mt][1][e] * cv.y;
        }
        float2 xr0 = *reinterpret_cast<const float2*>(&x[gr0 + col]);
        float2 xr1 = *reinterpret_cast<const float2*>(&x[gr1 + col]);
        float2 o0 = make_float2(acc[mt][nt][0] - c00 + xr0.x, acc[mt][nt][1] - c01 + xr0.y);
        float2 o1 = make_float2(acc[mt][nt][2] - c10 + xr1.x, acc[mt][nt][3] - c11 + xr1.y);
        *reinterpret_cast<float2*>(&out[gr0 + col]) = o0;
        *reinterpret_cast<float2*>(&out[gr1 + col]) = o1;
      }
    }
  }
}

// ---------------------------------------------------------------------------
extern "C" void kernel_launch(void* const* d_in, const int* in_sizes, int n_in,
                              void* d_out, int out_size) {
  const float* x   = (const float*)d_in[0];
  const float* wgA = (const float*)d_in[1];
  const float* weA = (const float*)d_in[2];
  const float* beA = (const float*)d_in[3];
  const float* wgB = (const float*)d_in[4];
  const float* weB = (const float*)d_in[5];
  const float* beB = (const float*)d_in[6];
  float* out = (float*)d_out;

  prep_kernel<<<64, 256>>>(wgA, weA, beA, wgB, weB, beB);

  int nTok   = in_sizes[0] / 64;
  int blocks = nTok / TOK;                 // 524288/128 = 4096
  size_t smem = sizeof(Smem);              // ~92 KB -> 2 CTAs/SM

  cudaFuncSetAttribute(moe2_kernel, cudaFuncAttributeMaxDynamicSharedMemorySize, (int)smem);
  moe2_kernel<<<blocks, TPB, smem>>>(x, out);
}